// round 6
// baseline (speedup 1.0000x reference)
#include <cuda_runtime.h>
#include <cuda_bf16.h>
#include <math.h>

// PositionCollapseLoss fused single-kernel version.
// Per batch: covariance of pos (channels 0:3 of 14), 3x3 symmetric eigvals,
// loss = -mean(log(clip(lmax/lmin, 1, 1e6))).
//
// Every block computes 9 raw fp32 moments for its (batch, chunk) slice and
// publishes them; the LAST block to finish (atomic ticket) runs the finalize
// inline (L2-hot partials), eliminating the second kernel launch.

#define B_DIM   32
#define N_PTS   65536
#define N_CH    14
#define CHUNKS  32          // blocks per batch; one warp lane per chunk
#define THREADS 256
#define PTS_PER_BLK (N_PTS / CHUNKS)   // 2048
#define GRID    (B_DIM * CHUNKS)       // 1024

__device__ float g_part[GRID][9];
__device__ unsigned int g_ticket = 0;   // reset by winner each run -> graph-safe

__device__ __forceinline__ float sanitize_f(float x) {
    if (isnan(x)) x = 0.0f;
    if (x >  1.0e6f) x =  1.0e6f;
    if (x < -1.0e6f) x = -1.0e6f;
    return x;
}

// Analytic eigen range of symmetric 3x3, then log(clip(ratio)).
__device__ __forceinline__ float batch_log_ratio(const float* s) {
    const float invN = 1.0f / (float)N_PTS;
    const float mx = s[0] * invN, my = s[1] * invN, mz = s[2] * invN;
    float cxx = sanitize_f(s[3] * invN - mx * mx);
    float cxy = sanitize_f(s[4] * invN - mx * my);
    float cxz = sanitize_f(s[5] * invN - mx * mz);
    float cyy = sanitize_f(s[6] * invN - my * my);
    float cyz = sanitize_f(s[7] * invN - my * mz);
    float czz = sanitize_f(s[8] * invN - mz * mz);

    const float q  = (cxx + cyy + czz) * (1.0f / 3.0f);
    const float p1 = cxy * cxy + cxz * cxz + cyz * cyz;
    const float d1 = cxx - q, d2 = cyy - q, d3 = czz - q;
    const float p2 = d1 * d1 + d2 * d2 + d3 * d3 + 2.0f * p1;

    float emax, emin;
    if (p2 <= 0.0f) {
        emax = q; emin = q;
    } else {
        const float p  = sqrtf(p2 * (1.0f / 6.0f));
        const float ip = 1.0f / p;
        const float b11 = d1 * ip, b22 = d2 * ip, b33 = d3 * ip;
        const float b12 = cxy * ip, b13 = cxz * ip, b23 = cyz * ip;
        float detB = b11 * (b22 * b33 - b23 * b23)
                   - b12 * (b12 * b33 - b23 * b13)
                   + b13 * (b12 * b23 - b22 * b13);
        float r = detB * 0.5f;
        r = fminf(1.0f, fmaxf(-1.0f, r));
        const float phi = acosf(r) * (1.0f / 3.0f);
        emax = q + 2.0f * p * cosf(phi);
        emin = q + 2.0f * p * cosf(phi + 2.0943951023931953f); // +2pi/3
    }

    emax = fmaxf(sanitize_f(emax), 1e-6f);
    emin = fmaxf(sanitize_f(emin), 1e-6f);
    float ratio = emax / emin;
    ratio = fminf(1.0e6f, fmaxf(1.0f, ratio));
    return logf(ratio);
}

__global__ __launch_bounds__(THREADS)
void fused_kernel(const float* __restrict__ g, float* __restrict__ out) {
    const int blk = blockIdx.x;                 // 0 .. GRID-1
    const int b   = blk / CHUNKS;
    const int c   = blk % CHUNKS;
    const int n0  = c * PTS_PER_BLK;

    const float* __restrict__ base = g + (size_t)b * (N_PTS * N_CH);

    float sx = 0.f, sy = 0.f, sz = 0.f;
    float sxx = 0.f, sxy = 0.f, sxz = 0.f;
    float syy = 0.f, syz = 0.f, szz = 0.f;

    #pragma unroll
    for (int it = 0; it < PTS_PER_BLK / THREADS; ++it) {
        const int i = n0 + it * THREADS + threadIdx.x;
        const int off = i * N_CH;               // < 13M, fits int
        // 56-byte point stride => always 8-byte aligned: float2 + scalar.
        // __ldcs: streaming, no reuse (117 MB ~ L2 capacity).
        const float2 xy = __ldcs(reinterpret_cast<const float2*>(base + off));
        const float  z  = __ldcs(base + off + 2);
        const float x = xy.x, y = xy.y;
        sx += x;  sy += y;  sz += z;
        sxx += x * x;  sxy += x * y;  sxz += x * z;
        syy += y * y;  syz += y * z;  szz += z * z;
    }

    float s[9] = {sx, sy, sz, sxx, sxy, sxz, syy, syz, szz};

    #pragma unroll
    for (int k = 0; k < 9; ++k) {
        #pragma unroll
        for (int m = 16; m > 0; m >>= 1)
            s[k] += __shfl_xor_sync(0xffffffffu, s[k], m);
    }

    __shared__ float sm[THREADS / 32][9];
    const int warp = threadIdx.x >> 5;
    const int lane = threadIdx.x & 31;
    if (lane == 0) {
        #pragma unroll
        for (int k = 0; k < 9; ++k) sm[warp][k] = s[k];
    }
    __syncthreads();

    if (warp == 0) {
        #pragma unroll
        for (int k = 0; k < 9; ++k) {
            float v = (lane < (THREADS / 32)) ? sm[lane][k] : 0.f;
            #pragma unroll
            for (int m = 4; m > 0; m >>= 1)
                v += __shfl_xor_sync(0xffffffffu, v, m);
            if (lane == 0) g_part[blk][k] = v;
        }
    }

    // ---- last-block-done handoff ----
    __shared__ unsigned int sh_is_last;
    __threadfence();                       // publish g_part[blk]
    __syncthreads();                       // all warps done (incl. writer warp)
    if (threadIdx.x == 0) {
        const unsigned int old = atomicAdd(&g_ticket, 1u);
        sh_is_last = (old == GRID - 1) ? 1u : 0u;
        if (sh_is_last) g_ticket = 0;      // reset for next graph replay
    }
    __syncthreads();
    if (!sh_is_last) return;

    __threadfence();                       // acquire: all g_part visible

    // ---- inline finalize: 8 warps, warp w handles batches w, w+8, w+16, w+24
    float lsum = 0.0f;
    #pragma unroll
    for (int rep = 0; rep < B_DIM / (THREADS / 32); ++rep) {
        const int bb = warp + rep * (THREADS / 32);
        float t[9];
        #pragma unroll
        for (int k = 0; k < 9; ++k) t[k] = g_part[bb * CHUNKS + lane][k];
        #pragma unroll
        for (int k = 0; k < 9; ++k) {
            #pragma unroll
            for (int m = 16; m > 0; m >>= 1)
                t[k] += __shfl_xor_sync(0xffffffffu, t[k], m);
        }
        if (lane == 0) lsum += batch_log_ratio(t);
    }

    __shared__ float sh_log[THREADS / 32];
    if (lane == 0) sh_log[warp] = lsum;
    __syncthreads();
    if (threadIdx.x == 0) {
        float l = 0.0f;
        #pragma unroll
        for (int w = 0; w < THREADS / 32; ++w) l += sh_log[w];
        out[0] = -l * (1.0f / (float)B_DIM);
    }
}

extern "C" void kernel_launch(void* const* d_in, const int* in_sizes, int n_in,
                              void* d_out, int out_size) {
    (void)in_sizes; (void)n_in; (void)out_size;
    const float* g = (const float*)d_in[0];
    float* out = (float*)d_out;
    fused_kernel<<<GRID, THREADS>>>(g, out);
}

// round 7
// speedup vs baseline: 1.0707x; 1.0707x over previous
#include <cuda_runtime.h>
#include <cuda_bf16.h>
#include <math.h>

// PositionCollapseLoss fused single-kernel version.
// Per batch: covariance of pos (channels 0:3 of 14), 3x3 symmetric eigvals,
// loss = -mean(log(clip(lmax/lmin, 1, 1e6))).
//
// Every block computes 9 raw fp32 moments for its (batch, chunk) slice and
// publishes them; the LAST block to finish (atomic ticket) runs the finalize
// inline (L2-hot partials), eliminating the second kernel launch.
//
// NOTE: loads are default-cached (.ca). __ldcs regressed R6 by forcing
// full-128B-line DRAM fetches (121 MB vs 84 MB of needed 32B sectors).

#define B_DIM   32
#define N_PTS   65536
#define N_CH    14
#define CHUNKS  32          // blocks per batch; one warp lane per chunk
#define THREADS 256
#define PTS_PER_BLK (N_PTS / CHUNKS)   // 2048
#define GRID    (B_DIM * CHUNKS)       // 1024

__device__ float g_part[GRID][9];
__device__ unsigned int g_ticket = 0;   // reset by winner each run -> graph-safe

__device__ __forceinline__ float sanitize_f(float x) {
    if (isnan(x)) x = 0.0f;
    if (x >  1.0e6f) x =  1.0e6f;
    if (x < -1.0e6f) x = -1.0e6f;
    return x;
}

// Analytic eigen range of symmetric 3x3, then log(clip(ratio)).
__device__ __forceinline__ float batch_log_ratio(const float* s) {
    const float invN = 1.0f / (float)N_PTS;
    const float mx = s[0] * invN, my = s[1] * invN, mz = s[2] * invN;
    float cxx = sanitize_f(s[3] * invN - mx * mx);
    float cxy = sanitize_f(s[4] * invN - mx * my);
    float cxz = sanitize_f(s[5] * invN - mx * mz);
    float cyy = sanitize_f(s[6] * invN - my * my);
    float cyz = sanitize_f(s[7] * invN - my * mz);
    float czz = sanitize_f(s[8] * invN - mz * mz);

    const float q  = (cxx + cyy + czz) * (1.0f / 3.0f);
    const float p1 = cxy * cxy + cxz * cxz + cyz * cyz;
    const float d1 = cxx - q, d2 = cyy - q, d3 = czz - q;
    const float p2 = d1 * d1 + d2 * d2 + d3 * d3 + 2.0f * p1;

    float emax, emin;
    if (p2 <= 0.0f) {
        emax = q; emin = q;
    } else {
        const float p  = sqrtf(p2 * (1.0f / 6.0f));
        const float ip = 1.0f / p;
        const float b11 = d1 * ip, b22 = d2 * ip, b33 = d3 * ip;
        const float b12 = cxy * ip, b13 = cxz * ip, b23 = cyz * ip;
        float detB = b11 * (b22 * b33 - b23 * b23)
                   - b12 * (b12 * b33 - b23 * b13)
                   + b13 * (b12 * b23 - b22 * b13);
        float r = detB * 0.5f;
        r = fminf(1.0f, fmaxf(-1.0f, r));
        const float phi = acosf(r) * (1.0f / 3.0f);
        emax = q + 2.0f * p * cosf(phi);
        emin = q + 2.0f * p * cosf(phi + 2.0943951023931953f); // +2pi/3
    }

    emax = fmaxf(sanitize_f(emax), 1e-6f);
    emin = fmaxf(sanitize_f(emin), 1e-6f);
    float ratio = emax / emin;
    ratio = fminf(1.0e6f, fmaxf(1.0f, ratio));
    return logf(ratio);
}

__global__ __launch_bounds__(THREADS)
void fused_kernel(const float* __restrict__ g, float* __restrict__ out) {
    const int blk = blockIdx.x;                 // 0 .. GRID-1
    const int b   = blk / CHUNKS;
    const int c   = blk % CHUNKS;
    const int n0  = c * PTS_PER_BLK;

    const float* __restrict__ base = g + (size_t)b * (N_PTS * N_CH);

    float sx = 0.f, sy = 0.f, sz = 0.f;
    float sxx = 0.f, sxy = 0.f, sxz = 0.f;
    float syy = 0.f, syz = 0.f, szz = 0.f;

    #pragma unroll
    for (int it = 0; it < PTS_PER_BLK / THREADS; ++it) {
        const int i = n0 + it * THREADS + threadIdx.x;
        const int off = i * N_CH;               // < 13M, fits int
        // 56-byte point stride => always 8-byte aligned: float2 + scalar.
        // Default cached loads: 32B-sector DRAM granularity (5/7 sectors).
        const float2 xy = *reinterpret_cast<const float2*>(base + off);
        const float  z  = base[off + 2];
        const float x = xy.x, y = xy.y;
        sx += x;  sy += y;  sz += z;
        sxx += x * x;  sxy += x * y;  sxz += x * z;
        syy += y * y;  syz += y * z;  szz += z * z;
    }

    float s[9] = {sx, sy, sz, sxx, sxy, sxz, syy, syz, szz};

    #pragma unroll
    for (int k = 0; k < 9; ++k) {
        #pragma unroll
        for (int m = 16; m > 0; m >>= 1)
            s[k] += __shfl_xor_sync(0xffffffffu, s[k], m);
    }

    __shared__ float sm[THREADS / 32][9];
    const int warp = threadIdx.x >> 5;
    const int lane = threadIdx.x & 31;
    if (lane == 0) {
        #pragma unroll
        for (int k = 0; k < 9; ++k) sm[warp][k] = s[k];
    }
    __syncthreads();

    if (warp == 0) {
        #pragma unroll
        for (int k = 0; k < 9; ++k) {
            float v = (lane < (THREADS / 32)) ? sm[lane][k] : 0.f;
            #pragma unroll
            for (int m = 4; m > 0; m >>= 1)
                v += __shfl_xor_sync(0xffffffffu, v, m);
            if (lane == 0) g_part[blk][k] = v;
        }
    }

    // ---- last-block-done handoff ----
    __shared__ unsigned int sh_is_last;
    __threadfence();                       // publish g_part[blk]
    __syncthreads();                       // all warps done (incl. writer warp)
    if (threadIdx.x == 0) {
        const unsigned int old = atomicAdd(&g_ticket, 1u);
        sh_is_last = (old == GRID - 1) ? 1u : 0u;
        if (sh_is_last) g_ticket = 0;      // reset for next graph replay
    }
    __syncthreads();
    if (!sh_is_last) return;

    __threadfence();                       // acquire: all g_part visible

    // ---- inline finalize: 8 warps, warp w handles batches w, w+8, w+16, w+24
    float lsum = 0.0f;
    #pragma unroll
    for (int rep = 0; rep < B_DIM / (THREADS / 32); ++rep) {
        const int bb = warp + rep * (THREADS / 32);
        float t[9];
        #pragma unroll
        for (int k = 0; k < 9; ++k) t[k] = g_part[bb * CHUNKS + lane][k];
        #pragma unroll
        for (int k = 0; k < 9; ++k) {
            #pragma unroll
            for (int m = 16; m > 0; m >>= 1)
                t[k] += __shfl_xor_sync(0xffffffffu, t[k], m);
        }
        if (lane == 0) lsum += batch_log_ratio(t);
    }

    __shared__ float sh_log[THREADS / 32];
    if (lane == 0) sh_log[warp] = lsum;
    __syncthreads();
    if (threadIdx.x == 0) {
        float l = 0.0f;
        #pragma unroll
        for (int w = 0; w < THREADS / 32; ++w) l += sh_log[w];
        out[0] = -l * (1.0f / (float)B_DIM);
    }
}

extern "C" void kernel_launch(void* const* d_in, const int* in_sizes, int n_in,
                              void* d_out, int out_size) {
    (void)in_sizes; (void)n_in; (void)out_size;
    const float* g = (const float*)d_in[0];
    float* out = (float*)d_out;
    fused_kernel<<<GRID, THREADS>>>(g, out);
}

// round 9
// speedup vs baseline: 1.1994x; 1.1202x over previous
#include <cuda_runtime.h>
#include <cuda_bf16.h>
#include <math.h>

// PositionCollapseLoss, two-kernel version (fused last-block variant regressed).
// Kernel 1: 9 raw fp32 moments per (batch, chunk), loads front-batched for MLP.
// Kernel 2: fp32 parallel finalize (warp per batch, analytic 3x3 eigvals).

#define B_DIM   32
#define N_PTS   65536
#define N_CH    14
#define CHUNKS  32          // blocks per batch; one warp lane per chunk
#define THREADS 256
#define PTS_PER_BLK (N_PTS / CHUNKS)   // 2048
#define ITERS   (PTS_PER_BLK / THREADS) // 8

__device__ float g_part[B_DIM * CHUNKS][9];

__global__ __launch_bounds__(THREADS)
void moments_kernel(const float* __restrict__ g) {
    const int blk = blockIdx.x;                 // 0 .. B*CHUNKS-1
    const int b   = blk / CHUNKS;
    const int c   = blk % CHUNKS;
    const int n0  = c * PTS_PER_BLK;

    const float* __restrict__ base = g + (size_t)b * (N_PTS * N_CH);

    // ---- front-batch ALL loads (max MLP), then accumulate ----
    float2 vxy[ITERS];
    float  vz[ITERS];
    #pragma unroll
    for (int it = 0; it < ITERS; ++it) {
        const int i   = n0 + it * THREADS + threadIdx.x;
        const int off = i * N_CH;               // < 13M, fits int
        // 56-byte point stride => always 8-byte aligned: float2 + scalar
        vxy[it] = *reinterpret_cast<const float2*>(base + off);
        vz[it]  = base[off + 2];
    }

    float sx = 0.f, sy = 0.f, sz = 0.f;
    float sxx = 0.f, sxy = 0.f, sxz = 0.f;
    float syy = 0.f, syz = 0.f, szz = 0.f;
    #pragma unroll
    for (int it = 0; it < ITERS; ++it) {
        const float x = vxy[it].x, y = vxy[it].y, z = vz[it];
        sx += x;  sy += y;  sz += z;
        sxx += x * x;  sxy += x * y;  sxz += x * z;
        syy += y * y;  syz += y * z;  szz += z * z;
    }

    float s[9] = {sx, sy, sz, sxx, sxy, sxz, syy, syz, szz};

    #pragma unroll
    for (int k = 0; k < 9; ++k) {
        #pragma unroll
        for (int m = 16; m > 0; m >>= 1)
            s[k] += __shfl_xor_sync(0xffffffffu, s[k], m);
    }

    __shared__ float sm[THREADS / 32][9];
    const int warp = threadIdx.x >> 5;
    const int lane = threadIdx.x & 31;
    if (lane == 0) {
        #pragma unroll
        for (int k = 0; k < 9; ++k) sm[warp][k] = s[k];
    }
    __syncthreads();

    if (warp == 0) {
        #pragma unroll
        for (int k = 0; k < 9; ++k) {
            float v = (lane < (THREADS / 32)) ? sm[lane][k] : 0.f;
            #pragma unroll
            for (int m = 4; m > 0; m >>= 1)
                v += __shfl_xor_sync(0xffffffffu, v, m);
            if (lane == 0) g_part[blk][k] = v;
        }
    }
}

__device__ __forceinline__ float sanitize_f(float x) {
    if (isnan(x)) x = 0.0f;
    if (x >  1.0e6f) x =  1.0e6f;
    if (x < -1.0e6f) x = -1.0e6f;
    return x;
}

__global__ __launch_bounds__(B_DIM * CHUNKS)
void finalize_kernel(float* __restrict__ out) {
    const int b    = threadIdx.x >> 5;   // batch = warp
    const int lane = threadIdx.x & 31;   // chunk = lane

    float s[9];
    #pragma unroll
    for (int k = 0; k < 9; ++k) s[k] = g_part[b * CHUNKS + lane][k];

    #pragma unroll
    for (int k = 0; k < 9; ++k) {
        #pragma unroll
        for (int m = 16; m > 0; m >>= 1)
            s[k] += __shfl_xor_sync(0xffffffffu, s[k], m);
    }

    __shared__ float sh_log[B_DIM];

    if (lane == 0) {
        const float invN = 1.0f / (float)N_PTS;
        const float mx = s[0] * invN, my = s[1] * invN, mz = s[2] * invN;
        float cxx = sanitize_f(s[3] * invN - mx * mx);
        float cxy = sanitize_f(s[4] * invN - mx * my);
        float cxz = sanitize_f(s[5] * invN - mx * mz);
        float cyy = sanitize_f(s[6] * invN - my * my);
        float cyz = sanitize_f(s[7] * invN - my * mz);
        float czz = sanitize_f(s[8] * invN - mz * mz);

        const float q  = (cxx + cyy + czz) * (1.0f / 3.0f);
        const float p1 = cxy * cxy + cxz * cxz + cyz * cyz;
        const float d1 = cxx - q, d2 = cyy - q, d3 = czz - q;
        const float p2 = d1 * d1 + d2 * d2 + d3 * d3 + 2.0f * p1;

        float emax, emin;
        if (p2 <= 0.0f) {
            emax = q; emin = q;
        } else {
            const float p  = sqrtf(p2 * (1.0f / 6.0f));
            const float ip = 1.0f / p;
            const float b11 = d1 * ip, b22 = d2 * ip, b33 = d3 * ip;
            const float b12 = cxy * ip, b13 = cxz * ip, b23 = cyz * ip;
            float detB = b11 * (b22 * b33 - b23 * b23)
                       - b12 * (b12 * b33 - b23 * b13)
                       + b13 * (b12 * b23 - b22 * b13);
            float r = detB * 0.5f;
            r = fminf(1.0f, fmaxf(-1.0f, r));
            const float phi = acosf(r) * (1.0f / 3.0f);
            emax = q + 2.0f * p * cosf(phi);
            emin = q + 2.0f * p * cosf(phi + 2.0943951023931953f); // +2pi/3
        }

        emax = fmaxf(sanitize_f(emax), 1e-6f);
        emin = fmaxf(sanitize_f(emin), 1e-6f);
        float ratio = emax / emin;
        ratio = fminf(1.0e6f, fmaxf(1.0f, ratio));
        sh_log[b] = logf(ratio);
    }
    __syncthreads();

    if (threadIdx.x < 32) {
        float l = sh_log[threadIdx.x];
        #pragma unroll
        for (int m = 16; m > 0; m >>= 1)
            l += __shfl_xor_sync(0xffffffffu, l, m);
        if (threadIdx.x == 0) out[0] = -l * (1.0f / (float)B_DIM);
    }
}

extern "C" void kernel_launch(void* const* d_in, const int* in_sizes, int n_in,
                              void* d_out, int out_size) {
    (void)in_sizes; (void)n_in; (void)out_size;
    const float* g = (const float*)d_in[0];
    float* out = (float*)d_out;
    moments_kernel<<<B_DIM * CHUNKS, THREADS>>>(g);
    finalize_kernel<<<1, B_DIM * CHUNKS>>>(out);
}

// round 10
// speedup vs baseline: 1.2907x; 1.0761x over previous
#include <cuda_runtime.h>
#include <cuda_bf16.h>
#include <math.h>

// PositionCollapseLoss, two-kernel + PDL overlap.
// Kernel 1: 9 raw fp32 moments per (batch, chunk) (R4 loop, best measured).
// Kernel 2: fp32 finalize, launched with programmatic stream serialization so
//           its launch/setup overlaps kernel 1; griddepcontrol.wait gates the
//           actual g_part reads on kernel 1 completion.

#define B_DIM   32
#define N_PTS   65536
#define N_CH    14
#define CHUNKS  32          // blocks per batch; one warp lane per chunk
#define THREADS 256
#define PTS_PER_BLK (N_PTS / CHUNKS)   // 2048

__device__ float g_part[B_DIM * CHUNKS][9];

__global__ __launch_bounds__(THREADS)
void moments_kernel(const float* __restrict__ g) {
    // Release the dependent (finalize) launch immediately: its blocks spin in
    // griddepcontrol.wait, overlapping launch overhead with our execution.
    asm volatile("griddepcontrol.launch_dependents;");

    const int blk = blockIdx.x;                 // 0 .. B*CHUNKS-1
    const int b   = blk / CHUNKS;
    const int c   = blk % CHUNKS;
    const int n0  = c * PTS_PER_BLK;

    const float* __restrict__ base = g + (size_t)b * (N_PTS * N_CH);

    float sx = 0.f, sy = 0.f, sz = 0.f;
    float sxx = 0.f, sxy = 0.f, sxz = 0.f;
    float syy = 0.f, syz = 0.f, szz = 0.f;

    #pragma unroll
    for (int it = 0; it < PTS_PER_BLK / THREADS; ++it) {
        const int i = n0 + it * THREADS + threadIdx.x;
        const int off = i * N_CH;               // < 13M, fits int
        // 56-byte point stride => always 8-byte aligned: float2 + scalar
        const float2 xy = *reinterpret_cast<const float2*>(base + off);
        const float  z  = base[off + 2];
        const float x = xy.x, y = xy.y;
        sx += x;  sy += y;  sz += z;
        sxx += x * x;  sxy += x * y;  sxz += x * z;
        syy += y * y;  syz += y * z;  szz += z * z;
    }

    float s[9] = {sx, sy, sz, sxx, sxy, sxz, syy, syz, szz};

    #pragma unroll
    for (int k = 0; k < 9; ++k) {
        #pragma unroll
        for (int m = 16; m > 0; m >>= 1)
            s[k] += __shfl_xor_sync(0xffffffffu, s[k], m);
    }

    __shared__ float sm[THREADS / 32][9];
    const int warp = threadIdx.x >> 5;
    const int lane = threadIdx.x & 31;
    if (lane == 0) {
        #pragma unroll
        for (int k = 0; k < 9; ++k) sm[warp][k] = s[k];
    }
    __syncthreads();

    if (warp == 0) {
        #pragma unroll
        for (int k = 0; k < 9; ++k) {
            float v = (lane < (THREADS / 32)) ? sm[lane][k] : 0.f;
            #pragma unroll
            for (int m = 4; m > 0; m >>= 1)
                v += __shfl_xor_sync(0xffffffffu, v, m);
            if (lane == 0) g_part[blk][k] = v;
        }
    }
}

__device__ __forceinline__ float sanitize_f(float x) {
    if (isnan(x)) x = 0.0f;
    if (x >  1.0e6f) x =  1.0e6f;
    if (x < -1.0e6f) x = -1.0e6f;
    return x;
}

__global__ __launch_bounds__(B_DIM * CHUNKS)
void finalize_kernel(float* __restrict__ out) {
    // Block until the moments grid has fully completed (memory visible).
    asm volatile("griddepcontrol.wait;" ::: "memory");

    const int b    = threadIdx.x >> 5;   // batch = warp
    const int lane = threadIdx.x & 31;   // chunk = lane

    float s[9];
    #pragma unroll
    for (int k = 0; k < 9; ++k) s[k] = g_part[b * CHUNKS + lane][k];

    #pragma unroll
    for (int k = 0; k < 9; ++k) {
        #pragma unroll
        for (int m = 16; m > 0; m >>= 1)
            s[k] += __shfl_xor_sync(0xffffffffu, s[k], m);
    }

    __shared__ float sh_log[B_DIM];

    if (lane == 0) {
        const float invN = 1.0f / (float)N_PTS;
        const float mx = s[0] * invN, my = s[1] * invN, mz = s[2] * invN;
        float cxx = sanitize_f(s[3] * invN - mx * mx);
        float cxy = sanitize_f(s[4] * invN - mx * my);
        float cxz = sanitize_f(s[5] * invN - mx * mz);
        float cyy = sanitize_f(s[6] * invN - my * my);
        float cyz = sanitize_f(s[7] * invN - my * mz);
        float czz = sanitize_f(s[8] * invN - mz * mz);

        const float q  = (cxx + cyy + czz) * (1.0f / 3.0f);
        const float p1 = cxy * cxy + cxz * cxz + cyz * cyz;
        const float d1 = cxx - q, d2 = cyy - q, d3 = czz - q;
        const float p2 = d1 * d1 + d2 * d2 + d3 * d3 + 2.0f * p1;

        float emax, emin;
        if (p2 <= 0.0f) {
            emax = q; emin = q;
        } else {
            const float p  = sqrtf(p2 * (1.0f / 6.0f));
            const float ip = 1.0f / p;
            const float b11 = d1 * ip, b22 = d2 * ip, b33 = d3 * ip;
            const float b12 = cxy * ip, b13 = cxz * ip, b23 = cyz * ip;
            float detB = b11 * (b22 * b33 - b23 * b23)
                       - b12 * (b12 * b33 - b23 * b13)
                       + b13 * (b12 * b23 - b22 * b13);
            float r = detB * 0.5f;
            r = fminf(1.0f, fmaxf(-1.0f, r));
            const float phi = acosf(r) * (1.0f / 3.0f);
            emax = q + 2.0f * p * cosf(phi);
            emin = q + 2.0f * p * cosf(phi + 2.0943951023931953f); // +2pi/3
        }

        emax = fmaxf(sanitize_f(emax), 1e-6f);
        emin = fmaxf(sanitize_f(emin), 1e-6f);
        float ratio = emax / emin;
        ratio = fminf(1.0e6f, fmaxf(1.0f, ratio));
        sh_log[b] = logf(ratio);
    }
    __syncthreads();

    if (threadIdx.x < 32) {
        float l = sh_log[threadIdx.x];
        #pragma unroll
        for (int m = 16; m > 0; m >>= 1)
            l += __shfl_xor_sync(0xffffffffu, l, m);
        if (threadIdx.x == 0) out[0] = -l * (1.0f / (float)B_DIM);
    }
}

extern "C" void kernel_launch(void* const* d_in, const int* in_sizes, int n_in,
                              void* d_out, int out_size) {
    (void)in_sizes; (void)n_in; (void)out_size;
    const float* g = (const float*)d_in[0];
    float* out = (float*)d_out;

    moments_kernel<<<B_DIM * CHUNKS, THREADS>>>(g);

    // Finalize with Programmatic Dependent Launch: launch overlaps moments.
    cudaLaunchConfig_t cfg = {};
    cfg.gridDim  = dim3(1, 1, 1);
    cfg.blockDim = dim3(B_DIM * CHUNKS, 1, 1);
    cfg.dynamicSmemBytes = 0;
    cfg.stream = 0;
    cudaLaunchAttribute attrs[1];
    attrs[0].id = cudaLaunchAttributeProgrammaticStreamSerialization;
    attrs[0].val.programmaticStreamSerializationAllowed = 1;
    cfg.attrs = attrs;
    cfg.numAttrs = 1;
    cudaLaunchKernelEx(&cfg, finalize_kernel, out);
}